// round 3
// baseline (speedup 1.0000x reference)
#include <cuda_runtime.h>
#include <cstddef>

// GATNE-T, two-kernel design.
// K1: neighbor gather + attention (weights selected by types[b]) -> natt[B,32]
// K2: type-grouped projection (weights register-resident) + base add + l2norm
//
// Inputs (metadata order):
//  0 targets   int32  [B]
//  1 types     int32  [B]
//  2 neighbors int32  [B,T,S]
//  3 base_node_embeddings float [V,E]
//  4 node_type_embeddings float [V,T,D]
//  5 trans_weights    float [T,D,E]
//  6 trans_weights_s1 float [T,D,A]
//  7 trans_weights_s2 float [T,A,1]
// Output: float [B,E]

namespace {
constexpr int T = 4;
constexpr int S = 10;
constexpr int D = 32;
constexpr int E = 128;
constexpr int A = 32;
constexpr int MAXB = 8192;
constexpr int G1 = 8;     // batch elements per CTA in K1
}

__device__ float g_natt[MAXB * D];   // attended node embedding per b

// ---------------------------------------------------------------------------
// K1: gather + attention.  128 threads = 4 warps.
// Gather phase:   warp = edge type t, lane = dim d.
// Attention phase: the single warp whose cached type == types[b] computes all
//                  four u-rows (lane = a), softmax, and natt (lane = d).
// Each warp register-caches W1[:, lane] and w2[lane] for ITS OWN type, so the
// per-b attention weights (selected by types[b]) are always in registers of
// exactly one warp.
// ---------------------------------------------------------------------------
__global__ __launch_bounds__(128) void k1_gather_attn(
    const int*   __restrict__ types,
    const int*   __restrict__ neighbors,  // [B,T,S]
    const float* __restrict__ nte,        // [V,T,D]
    const float* __restrict__ tw1,        // [T,D,A]
    const float* __restrict__ tw2,        // [T,A]
    int B)
{
    const int warp = threadIdx.x >> 5;
    const int lane = threadIdx.x & 31;

    __shared__ float sh_agg[T][D];
    __shared__ int   sh_ty[G1];

    // Register-cached attention weights for THIS warp's type (= warp id).
    float w1reg[D];
    {
        const float* w1 = tw1 + warp * (D * A);
        #pragma unroll
        for (int d = 0; d < D; ++d) w1reg[d] = w1[d * A + lane];
    }
    const float tw2v = tw2[warp * A + lane];

    const int b0 = blockIdx.x * G1;
    if (threadIdx.x < G1 && b0 + threadIdx.x < B)
        sh_ty[threadIdx.x] = types[b0 + threadIdx.x];
    __syncthreads();

    #pragma unroll 1
    for (int g = 0; g < G1; ++g) {
        const int b = b0 + g;
        if (b >= B) return;               // uniform across CTA

        // ---- neighbor gather + mean: warp t, lane d ----
        int nbv = 0;
        if (lane < S) nbv = neighbors[b * (T * S) + warp * S + lane];

        float acc = 0.0f;
        #pragma unroll
        for (int s = 0; s < S; ++s) {
            const int v = __shfl_sync(0xffffffffu, nbv, s);
            acc += __ldg(&nte[(size_t)v * (T * D) + warp * D + lane]);
        }
        sh_agg[warp][lane] = acc * (1.0f / (float)S);
        __syncthreads();

        // ---- attention: only the warp owning types[b]'s weights works ----
        if (warp == sh_ty[g]) {
            float score[T];
            #pragma unroll
            for (int t = 0; t < T; ++t) {
                // lane = a: dot_a = sum_d agg[t][d] * W1[type][d][a]
                float dot = 0.0f;
                const float4* ap = (const float4*)sh_agg[t];
                #pragma unroll
                for (int q = 0; q < D / 4; ++q) {
                    const float4 v4 = ap[q];          // broadcast LDS.128
                    dot = fmaf(v4.x, w1reg[4 * q + 0], dot);
                    dot = fmaf(v4.y, w1reg[4 * q + 1], dot);
                    dot = fmaf(v4.z, w1reg[4 * q + 2], dot);
                    dot = fmaf(v4.w, w1reg[4 * q + 3], dot);
                }
                float u = tanhf(dot) * tw2v;
                #pragma unroll
                for (int off = 16; off > 0; off >>= 1)
                    u += __shfl_xor_sync(0xffffffffu, u, off);
                score[t] = u;                          // same in every lane
            }

            // softmax over T=4, then natt[d] (lane = d)
            const float m  = fmaxf(fmaxf(score[0], score[1]),
                                   fmaxf(score[2], score[3]));
            const float e0 = __expf(score[0] - m), e1 = __expf(score[1] - m);
            const float e2 = __expf(score[2] - m), e3 = __expf(score[3] - m);
            const float inv = 1.0f / (e0 + e1 + e2 + e3);
            const float natt = (e0 * sh_agg[0][lane] + e1 * sh_agg[1][lane] +
                                e2 * sh_agg[2][lane] + e3 * sh_agg[3][lane]) * inv;
            g_natt[b * D + lane] = natt;
        }
        __syncthreads();                   // sh_agg reused next iteration
    }
}

// ---------------------------------------------------------------------------
// K2: projection + base add + l2 normalize, type-grouped.
// 256 threads = 8 warps. Warp w handles type (w&3) on sub-stripe (w>>2).
// Each warp holds its type's FULL 32x128 projection matrix in registers
// (float4 per lane per d => 128 regs), loaded once per CTA.
// ---------------------------------------------------------------------------
__global__ __launch_bounds__(256, 1) void k2_proj_norm(
    const int*   __restrict__ targets,
    const int*   __restrict__ types,
    const float* __restrict__ base_emb,   // [V,E]
    const float* __restrict__ tw,         // [T,D,E]
    float*       __restrict__ out,        // [B,E]
    int B, int chunk)
{
    __shared__ int sh_ty[64];

    const int tid  = threadIdx.x;
    const int warp = tid >> 5;
    const int lane = tid & 31;

    const int b0 = blockIdx.x * chunk;
    if (b0 >= B) return;
    const int nb = min(chunk, B - b0);

    for (int i = tid; i < nb; i += 256) sh_ty[i] = types[b0 + i];
    __syncthreads();

    const int myt = warp & 3;
    const int sub = warp >> 2;  // 0 or 1: interleaved halves of the chunk

    // Register-resident projection weights: wreg[d] = tw[myt][d][lane*4 .. +3]
    float4 wreg[D];
    {
        const float4* wp = (const float4*)(tw + (size_t)myt * (D * E));
        #pragma unroll
        for (int d = 0; d < D; ++d) wreg[d] = wp[d * (E / 4) + lane];
    }

    for (int i = sub; i < nb; i += 2) {
        if (sh_ty[i] != myt) continue;     // uniform across warp
        const int b = b0 + i;

        // natt broadcast into registers (8 x 128-bit broadcast loads)
        const float4* np = (const float4*)(g_natt + b * D);
        float4 acc = make_float4(0.f, 0.f, 0.f, 0.f);
        #pragma unroll
        for (int q = 0; q < D / 4; ++q) {
            const float4 n4 = np[q];
            const float4 w0 = wreg[4 * q + 0];
            const float4 w1 = wreg[4 * q + 1];
            const float4 w2 = wreg[4 * q + 2];
            const float4 w3 = wreg[4 * q + 3];
            acc.x = fmaf(n4.x, w0.x, acc.x); acc.y = fmaf(n4.x, w0.y, acc.y);
            acc.z = fmaf(n4.x, w0.z, acc.z); acc.w = fmaf(n4.x, w0.w, acc.w);
            acc.x = fmaf(n4.y, w1.x, acc.x); acc.y = fmaf(n4.y, w1.y, acc.y);
            acc.z = fmaf(n4.y, w1.z, acc.z); acc.w = fmaf(n4.y, w1.w, acc.w);
            acc.x = fmaf(n4.z, w2.x, acc.x); acc.y = fmaf(n4.z, w2.y, acc.y);
            acc.z = fmaf(n4.z, w2.z, acc.z); acc.w = fmaf(n4.z, w2.w, acc.w);
            acc.x = fmaf(n4.w, w3.x, acc.x); acc.y = fmaf(n4.w, w3.y, acc.y);
            acc.z = fmaf(n4.w, w3.z, acc.z); acc.w = fmaf(n4.w, w3.w, acc.w);
        }

        const int tgt = targets[b];
        const float4 bv = ((const float4*)(base_emb + (size_t)tgt * E))[lane];
        float4 val = make_float4(acc.x + bv.x, acc.y + bv.y,
                                 acc.z + bv.z, acc.w + bv.w);

        float ss = val.x * val.x + val.y * val.y + val.z * val.z + val.w * val.w;
        #pragma unroll
        for (int off = 16; off > 0; off >>= 1)
            ss += __shfl_xor_sync(0xffffffffu, ss, off);
        const float r = rsqrtf(fmaxf(ss, 1e-12f));

        const float4 o = make_float4(val.x * r, val.y * r, val.z * r, val.w * r);
        ((float4*)(out + (size_t)b * E))[lane] = o;
    }
}

extern "C" void kernel_launch(void* const* d_in, const int* in_sizes, int n_in,
                              void* d_out, int out_size) {
    const int*   targets   = (const int*)  d_in[0];
    const int*   types     = (const int*)  d_in[1];
    const int*   neighbors = (const int*)  d_in[2];
    const float* base_emb  = (const float*)d_in[3];
    const float* nte       = (const float*)d_in[4];
    const float* tw        = (const float*)d_in[5];
    const float* tw1       = (const float*)d_in[6];
    const float* tw2       = (const float*)d_in[7];
    float* out = (float*)d_out;

    const int B = in_sizes[0];

    const int grid1 = (B + G1 - 1) / G1;
    k1_gather_attn<<<grid1, 128>>>(types, neighbors, nte, tw1, tw2, B);

    const int grid2 = 152;                       // ~1 CTA per SM
    const int chunk = (B + grid2 - 1) / grid2;   // <= 64 for B=8192
    k2_proj_norm<<<grid2, 256>>>(targets, types, base_emb, tw, out, B, chunk);
}